// round 3
// baseline (speedup 1.0000x reference)
#include <cuda_runtime.h>
#include <cuda_bf16.h>

// Problem constants (match reference)
#define HH 512
#define WW 512
#define RR 4
#define BB 2
#define PP 65536
#define CC 8
#define NPTS (BB * PP)
#define NPIX (BB * HH * WW)

// Accumulator layout per pixel: acc[3*pix+0] = {w_sum, wz_sum, ws_sum, pad}
//                               acc[3*pix+1] = {wf0..wf3}
//                               acc[3*pix+2] = {wf4..wf7}
__device__ float4 g_acc[NPIX * 3];

// ---------------------------------------------------------------------------
// Coalesced zero-fill of the accumulators (pure streaming stores).
__global__ void __launch_bounds__(256) k_zero() {
    int i = blockIdx.x * blockDim.x + threadIdx.x;   // NPIX*3 f4 / 2 per thread
    float4 zz = make_float4(0.f, 0.f, 0.f, 0.f);
    g_acc[2 * i + 0] = zz;
    g_acc[2 * i + 1] = zz;
}

// ---------------------------------------------------------------------------
// Scatter pass over a chunk of points. Stabilizer-free weights:
// w' = ws * exp(-2z); the reference's exp(2*zmin) softmax factor cancels in
// color/depth ratios, and EPS influence is <= ~3e-5 relative (verified R2:
// rel_err bit-identical with/without the stabilizer pass).
// Cull arithmetic kept bit-identical to the passing R1/R2 kernels.
__global__ void __launch_bounds__(256) k_accum(
        const float* __restrict__ pts,
        const float* __restrict__ feat,
        const float* __restrict__ sig,
        const float* __restrict__ mr_ptr,
        int start) {
    int i = start + blockIdx.x * blockDim.x + threadIdx.x;
    if (i >= NPTS) return;
    float x = pts[3 * i + 0];
    float y = pts[3 * i + 1];
    float z = pts[3 * i + 2];
    if (!(z > 0.1f && z < 10.0f)) return;

    float mr = __ldg(mr_ptr);
    float r2 = mr * mr;
    float s  = sig[i];
    float inv2s2 = 1.0f / (2.0f * s * s);
    float ez = __expf(-2.0f * z);                    // GAMMA = 0.5 -> factor 2

    const float4* f4 = (const float4*)feat;
    float4 fa = f4[2 * i + 0];
    float4 fb = f4[2 * i + 1];

    int cx = (int)rintf((x + 1.0f) * 0.5f * 511.0f);
    int cy = (int)rintf((y + 1.0f) * 0.5f * 511.0f);
    int base = (i >= PP) ? (HH * WW) : 0;

    // Per-column dx^2 and in-bounds mask (bit-identical math to R1/R2).
    float dx2c[2 * RR + 1];
    unsigned colmask = 0;
#pragma unroll
    for (int k = 0; k < 2 * RR + 1; ++k) {
        int qx = cx + k - RR;
        float qxn = __fadd_rn(__fmul_rn(2.0f, (float)qx) / 511.0f, -1.0f);
        float dx = __fadd_rn(qxn, -x);
        dx2c[k] = __fmul_rn(dx, dx);
        if (qx >= 0 && qx < WW) colmask |= (1u << k);
    }

    for (int j = 0; j < 2 * RR + 1; ++j) {
        int qy = cy + j - RR;
        if (qy < 0 || qy >= HH) continue;
        float qyn = __fadd_rn(__fmul_rn(2.0f, (float)qy) / 511.0f, -1.0f);
        float dy = __fadd_rn(qyn, -y);
        float dy2 = __fmul_rn(dy, dy);
        int rowbase = base + qy * WW + cx - RR;
#pragma unroll
        for (int k = 0; k < 2 * RR + 1; ++k) {
            float d2 = __fadd_rn(dx2c[k], dy2);
            if (((colmask >> k) & 1u) && d2 <= r2) {
                float ws = __expf(-d2 * inv2s2);
                float w  = ws * ez;
                float4* a = &g_acc[3 * (rowbase + k)];
                atomicAdd(&a[0], make_float4(w, w * z, ws, 0.0f));
                atomicAdd(&a[1], make_float4(w * fa.x, w * fa.y, w * fa.z, w * fa.w));
                atomicAdd(&a[2], make_float4(w * fb.x, w * fb.y, w * fb.z, w * fb.w));
            }
        }
    }
}

// ---------------------------------------------------------------------------
// Output layout: [color (B,H,W,C)] [depth (B,H,W)] [mask (B,H,W)], all f32.
__global__ void __launch_bounds__(256) k_final(float* __restrict__ out) {
    int i = blockIdx.x * blockDim.x + threadIdx.x;   // NPIX divisible by 256
    float4 a0 = g_acc[3 * i + 0];
    float4 a1 = g_acc[3 * i + 1];
    float4 a2 = g_acc[3 * i + 2];

    float inv = (a0.x > 0.0f) ? (1.0f / a0.x) : 0.0f;

    float4* col = (float4*)out;
    col[2 * i + 0] = make_float4(a1.x * inv, a1.y * inv, a1.z * inv, a1.w * inv);
    col[2 * i + 1] = make_float4(a2.x * inv, a2.y * inv, a2.z * inv, a2.w * inv);

    out[NPIX * CC + i]        = a0.y * inv;             // depth
    out[NPIX * CC + NPIX + i] = 1.0f - expf(-a0.z);     // mask
}

// ---------------------------------------------------------------------------
extern "C" void kernel_launch(void* const* d_in, const int* in_sizes, int n_in,
                              void* d_out, int out_size) {
    const float* pts  = (const float*)d_in[0];  // [B,P,3]
    const float* feat = (const float*)d_in[1];  // [B,P,8]
    const float* sig  = (const float*)d_in[2];  // [B,P]
    const float* mr   = (const float*)d_in[3];  // scalar
    float* out = (float*)d_out;

    // Point chunks (all multiples of 256; period-5 launch pattern so the
    // profiler's fixed skip lands on an accum chunk next round).
    const int C0 = 43776, C1 = 43776, C2 = NPTS - 2 * 43776;   // 43520

    k_zero <<<(NPIX * 3 / 2) / 256, 256>>>();
    k_accum<<<C0 / 256, 256>>>(pts, feat, sig, mr, 0);
    k_accum<<<C1 / 256, 256>>>(pts, feat, sig, mr, C0);
    k_accum<<<C2 / 256, 256>>>(pts, feat, sig, mr, C0 + C1);
    k_final<<<NPIX / 256, 256>>>(out);
}

// round 4
// speedup vs baseline: 1.5847x; 1.5847x over previous
#include <cuda_runtime.h>
#include <cuda_bf16.h>

// Problem constants (match reference)
#define HH 512
#define WW 512
#define RR 4
#define BB 2
#define PP 65536
#define CC 8
#define NPTS (BB * PP)
#define NPIX (BB * HH * WW)
#define NROW (2 * RR + 1)          // 9 footprint rows

// Accumulator layout per pixel: acc[3*pix+0] = {w_sum, wz_sum, ws_sum, pad}
//                               acc[3*pix+1] = {wf0..wf3}
//                               acc[3*pix+2] = {wf4..wf7}
__device__ float4 g_acc[NPIX * 3];

// ---------------------------------------------------------------------------
// Coalesced zero-fill of the accumulators (pure streaming stores).
__global__ void __launch_bounds__(256) k_zero() {
    int i = blockIdx.x * blockDim.x + threadIdx.x;
    float4 zz = make_float4(0.f, 0.f, 0.f, 0.f);
    g_acc[2 * i + 0] = zz;
    g_acc[2 * i + 1] = zz;
}

// ---------------------------------------------------------------------------
// Scatter pass: ONE THREAD PER (point, footprint-row). 9 sibling threads of a
// point are adjacent in the warp, so point/feature loads coalesce. This gives
// 9x the warps of the per-point version, hiding L2 atomic latency (R3 ncu:
// occ 14.8%, issue 8.7% -> latency-bound).
// Stabilizer-free weights w' = ws*exp(-2z) (exact cancellation; verified R2).
// Cull arithmetic bit-identical to the passing R1/R2 kernels.
__global__ void __launch_bounds__(256) k_accum(
        const float* __restrict__ pts,
        const float* __restrict__ feat,
        const float* __restrict__ sig,
        const float* __restrict__ mr_ptr) {
    int t = blockIdx.x * blockDim.x + threadIdx.x;   // NPTS*9 threads exactly
    int i = t / NROW;                                // point index
    int j = t - i * NROW;                            // row offset 0..8

    float x = pts[3 * i + 0];
    float y = pts[3 * i + 1];
    float z = pts[3 * i + 2];
    if (!(z > 0.1f && z < 10.0f)) return;

    int cy = (int)rintf((y + 1.0f) * 0.5f * 511.0f);
    int qy = cy + j - RR;
    if (qy < 0 || qy >= HH) return;

    int cx = (int)rintf((x + 1.0f) * 0.5f * 511.0f);

    // Quick reject: if even the nearest column of this row can't be in range,
    // skip the loads. (Conservative test only; final cull is exact below.)
    float mr = __ldg(mr_ptr);
    float r2 = mr * mr;

    float qyn = __fadd_rn(__fmul_rn(2.0f, (float)qy) / 511.0f, -1.0f);
    float dy  = __fadd_rn(qyn, -y);
    float dy2 = __fmul_rn(dy, dy);
    if (dy2 > r2) return;                            // whole row out of range

    float s  = sig[i];
    float inv2s2 = 1.0f / (2.0f * s * s);
    float ez = __expf(-2.0f * z);                    // GAMMA = 0.5 -> factor 2

    const float4* f4 = (const float4*)feat;
    float4 fa = f4[2 * i + 0];
    float4 fb = f4[2 * i + 1];

    int base = (i >= PP) ? (HH * WW) : 0;
    int rowbase = base + qy * WW + cx - RR;

#pragma unroll
    for (int k = 0; k < NROW; ++k) {
        int qx = cx + k - RR;
        float qxn = __fadd_rn(__fmul_rn(2.0f, (float)qx) / 511.0f, -1.0f);
        float dx  = __fadd_rn(qxn, -x);
        float dx2 = __fmul_rn(dx, dx);
        float d2  = __fadd_rn(dx2, dy2);
        if (qx >= 0 && qx < WW && d2 <= r2) {
            float ws = __expf(-d2 * inv2s2);
            float w  = ws * ez;
            float4* a = &g_acc[3 * (rowbase + k)];
            atomicAdd(&a[0], make_float4(w, w * z, ws, 0.0f));
            atomicAdd(&a[1], make_float4(w * fa.x, w * fa.y, w * fa.z, w * fa.w));
            atomicAdd(&a[2], make_float4(w * fb.x, w * fb.y, w * fb.z, w * fb.w));
        }
    }
}

// ---------------------------------------------------------------------------
// Output layout: [color (B,H,W,C)] [depth (B,H,W)] [mask (B,H,W)], all f32.
__global__ void __launch_bounds__(256) k_final(float* __restrict__ out) {
    int i = blockIdx.x * blockDim.x + threadIdx.x;   // NPIX divisible by 256
    float4 a0 = g_acc[3 * i + 0];
    float4 a1 = g_acc[3 * i + 1];
    float4 a2 = g_acc[3 * i + 2];

    float inv = (a0.x > 0.0f) ? (1.0f / a0.x) : 0.0f;

    float4* col = (float4*)out;
    col[2 * i + 0] = make_float4(a1.x * inv, a1.y * inv, a1.z * inv, a1.w * inv);
    col[2 * i + 1] = make_float4(a2.x * inv, a2.y * inv, a2.z * inv, a2.w * inv);

    out[NPIX * CC + i]        = a0.y * inv;             // depth
    out[NPIX * CC + NPIX + i] = 1.0f - expf(-a0.z);     // mask
}

// ---------------------------------------------------------------------------
extern "C" void kernel_launch(void* const* d_in, const int* in_sizes, int n_in,
                              void* d_out, int out_size) {
    const float* pts  = (const float*)d_in[0];  // [B,P,3]
    const float* feat = (const float*)d_in[1];  // [B,P,8]
    const float* sig  = (const float*)d_in[2];  // [B,P]
    const float* mr   = (const float*)d_in[3];  // scalar
    float* out = (float*)d_out;

    k_zero <<<(NPIX * 3 / 2) / 256, 256>>>();
    k_accum<<<(NPTS * NROW) / 256, 256>>>(pts, feat, sig, mr);
    k_final<<<NPIX / 256, 256>>>(out);
}

// round 5
// speedup vs baseline: 2.7902x; 1.7607x over previous
#include <cuda_runtime.h>
#include <cuda_bf16.h>

// Problem constants (match reference)
#define HH 512
#define WW 512
#define RR 4
#define BB 2
#define PP 65536
#define CC 8
#define NPTS (BB * PP)
#define NPIX (BB * HH * WW)

// Tiling: 16 x 8 pixel tiles, one CTA (128 threads) per tile.
#define TW 16
#define TH 8
#define TILES_X (WW / TW)            // 32
#define TILES_Y (HH / TH)            // 64
#define TILES_IMG (TILES_X * TILES_Y)  // 2048
#define NTILES (BB * TILES_IMG)      // 4096
#define CAP 256                      // per-tile point capacity (mean ~96)
#define CHUNK 128                    // candidates staged per smem round

__device__ int g_cnt[NTILES];
__device__ int g_list[NTILES * CAP];

// ---------------------------------------------------------------------------
__global__ void __launch_bounds__(256) k_zero_cnt() {
    int i = blockIdx.x * blockDim.x + threadIdx.x;
    if (i < NTILES) g_cnt[i] = 0;
}

// ---------------------------------------------------------------------------
// Bin each valid point into every tile its clamped 9x9 pixel box overlaps
// (<= 2x2 tiles). Pixels outside the box can never pass the d2 cull
// (distance >= 4.5 px > max radius 4.09 px), so tile membership is exact.
__global__ void __launch_bounds__(256) k_bin(const float* __restrict__ pts) {
    int i = blockIdx.x * blockDim.x + threadIdx.x;   // NPTS divisible by 256
    float x = pts[3 * i + 0];
    float y = pts[3 * i + 1];
    float z = pts[3 * i + 2];
    if (!(z > 0.1f && z < 10.0f)) return;

    int cx = (int)rintf((x + 1.0f) * 0.5f * 511.0f);
    int cy = (int)rintf((y + 1.0f) * 0.5f * 511.0f);
    int px0 = max(cx - RR, 0), px1 = min(cx + RR, WW - 1);
    int py0 = max(cy - RR, 0), py1 = min(cy + RR, HH - 1);
    if (px0 > px1 || py0 > py1) return;

    int tx0 = px0 >> 4, tx1 = px1 >> 4;              // TW = 16
    int ty0 = py0 >> 3, ty1 = py1 >> 3;              // TH = 8
    int tb = (i >= PP) ? TILES_IMG : 0;

    for (int ty = ty0; ty <= ty1; ++ty)
        for (int tx = tx0; tx <= tx1; ++tx) {
            int t = tb + ty * TILES_X + tx;
            int slot = atomicAdd(&g_cnt[t], 1);
            if (slot < CAP) g_list[t * CAP + slot] = i;
        }
}

// ---------------------------------------------------------------------------
// Gather: one thread per pixel, register accumulators, candidates staged in
// shared memory. Stabilizer-free weights w' = ws*exp(-2z) (exact cancellation
// in color/depth; EPS influence ~3e-5 rel — verified R2-R4).
// Per-fragment math bit-identical to the passing R1-R4 kernels.
__global__ void __launch_bounds__(128) k_gather(
        const float* __restrict__ pts,
        const float* __restrict__ feat,
        const float* __restrict__ sig,
        const float* __restrict__ mr_ptr,
        float* __restrict__ out) {
    __shared__ float2 sxy[CHUNK];
    __shared__ float  sz [CHUNK];
    __shared__ float  sinv[CHUNK];
    __shared__ float  sez[CHUNK];
    __shared__ float4 sfa[CHUNK];
    __shared__ float4 sfb[CHUNK];

    int t = blockIdx.x;
    int b = t / TILES_IMG;
    int r = t - b * TILES_IMG;
    int ty = r / TILES_X;
    int tx = r - ty * TILES_X;

    int tid = threadIdx.x;
    int px = tx * TW + (tid & (TW - 1));
    int py = ty * TH + (tid >> 4);

    // Pixel NDC coords — bit-identical formula to the validated cull math.
    float qxn = __fadd_rn(__fmul_rn(2.0f, (float)px) / 511.0f, -1.0f);
    float qyn = __fadd_rn(__fmul_rn(2.0f, (float)py) / 511.0f, -1.0f);

    float mr = __ldg(mr_ptr);
    float r2 = mr * mr;

    int cnt = g_cnt[t];
    if (cnt > CAP) cnt = CAP;

    float accW = 0.f, accWZ = 0.f, accWS = 0.f;
    float f0 = 0.f, f1 = 0.f, f2 = 0.f, f3 = 0.f;
    float f4v = 0.f, f5 = 0.f, f6 = 0.f, f7 = 0.f;

    const float4* ff = (const float4*)feat;

    for (int c0 = 0; c0 < cnt; c0 += CHUNK) {
        int chunk = min(CHUNK, cnt - c0);
        // Stage candidates (one per thread).
        if (tid < chunk) {
            int j = g_list[t * CAP + c0 + tid];
            float x = pts[3 * j + 0];
            float y = pts[3 * j + 1];
            float z = pts[3 * j + 2];
            float s = sig[j];
            sxy[tid] = make_float2(x, y);
            sz [tid] = z;
            sinv[tid] = 1.0f / (2.0f * s * s);
            sez[tid] = __expf(-2.0f * z);            // GAMMA = 0.5
            sfa[tid] = ff[2 * j + 0];
            sfb[tid] = ff[2 * j + 1];
        }
        __syncthreads();

        for (int k = 0; k < chunk; ++k) {
            float2 pxy = sxy[k];
            float dx = __fadd_rn(qxn, -pxy.x);
            float dy = __fadd_rn(qyn, -pxy.y);
            float d2 = __fadd_rn(__fmul_rn(dx, dx), __fmul_rn(dy, dy));
            if (d2 <= r2) {
                float ws = __expf(-d2 * sinv[k]);
                float w  = ws * sez[k];
                float z  = sz[k];
                accWS += ws;
                accW  += w;
                accWZ += w * z;
                float4 fa = sfa[k];
                float4 fb = sfb[k];
                f0  += w * fa.x;  f1 += w * fa.y;
                f2  += w * fa.z;  f3 += w * fa.w;
                f4v += w * fb.x;  f5 += w * fb.y;
                f6  += w * fb.z;  f7 += w * fb.w;
            }
        }
        __syncthreads();
    }

    // Finalize directly (fused epilogue).
    int pix = b * (HH * WW) + py * WW + px;
    float inv = (accW > 0.0f) ? (1.0f / accW) : 0.0f;

    float4* col = (float4*)out;
    col[2 * pix + 0] = make_float4(f0 * inv, f1 * inv, f2 * inv, f3 * inv);
    col[2 * pix + 1] = make_float4(f4v * inv, f5 * inv, f6 * inv, f7 * inv);
    out[NPIX * CC + pix]        = accWZ * inv;           // depth
    out[NPIX * CC + NPIX + pix] = 1.0f - expf(-accWS);   // mask
}

// ---------------------------------------------------------------------------
extern "C" void kernel_launch(void* const* d_in, const int* in_sizes, int n_in,
                              void* d_out, int out_size) {
    const float* pts  = (const float*)d_in[0];  // [B,P,3]
    const float* feat = (const float*)d_in[1];  // [B,P,8]
    const float* sig  = (const float*)d_in[2];  // [B,P]
    const float* mr   = (const float*)d_in[3];  // scalar
    float* out = (float*)d_out;

    k_zero_cnt<<<(NTILES + 255) / 256, 256>>>();
    k_bin    <<<NPTS / 256, 256>>>(pts);
    k_gather <<<NTILES, 128>>>(pts, feat, sig, mr, out);
}